// round 4
// baseline (speedup 1.0000x reference)
#include <cuda_runtime.h>
#include <math.h>

#define NN 50000
#define NE 800000
#define DIN 64
#define DH  128

// ---------------- device scratch (static, no allocation) ----------------
__device__ float g_bufA[NN * DIN];
__device__ float g_bufB[NN * DIN];
__device__ float g_agg[NN * DIN];
__device__ float g_h1[NN * DH];
__device__ int   g_src[NE];
__device__ int   g_dst[NE];
__device__ int   g_deg[NN];
__device__ int   g_off[NN + 1];
__device__ int   g_cur[NN];
__device__ int   g_csr[NE];
__device__ int   g_bsum[64];
__device__ int   g_is32;
__device__ float g_bn[2 * DH];
__device__ float g_scale[DH];
__device__ float g_shift[DH];

// ---------------- edge dtype detect + normalize ----------------
__global__ void k_detect(const void* __restrict__ ei) {
    if (threadIdx.x == 0 && blockIdx.x == 0) {
        const long long* p = (const long long*)ei;
        int is32 = 0;
        for (int i = 0; i < 256; i++) {
            long long v = p[i];
            if (v < 0 || v >= NN) { is32 = 1; break; }
        }
        g_is32 = is32;
    }
}

__global__ void k_convert(const void* __restrict__ ei) {
    int e = blockIdx.x * blockDim.x + threadIdx.x;
    if (e >= NE) return;
    int s, d;
    if (g_is32) {
        const int* p = (const int*)ei;
        s = p[e]; d = p[NE + e];
    } else {
        const long long* p = (const long long*)ei;
        s = (int)p[e]; d = (int)p[NE + e];
    }
    s = min(max(s, 0), NN - 1);
    d = min(max(d, 0), NN - 1);
    g_src[e] = s;
    g_dst[e] = d;
}

// ---------------- CSR build ----------------
__global__ void k_zero_deg() {
    int i = blockIdx.x * blockDim.x + threadIdx.x;
    if (i < NN) g_deg[i] = 0;
}

__global__ void k_hist() {
    int e = blockIdx.x * blockDim.x + threadIdx.x;
    if (e < NE) atomicAdd(&g_deg[g_dst[e]], 1);
}

__global__ void k_scan_local() {
    __shared__ int sh[1024];
    int tid = threadIdx.x;
    int gid = blockIdx.x * 1024 + tid;
    int v = (gid < NN) ? g_deg[gid] : 0;
    sh[tid] = v;
    __syncthreads();
    for (int o = 1; o < 1024; o <<= 1) {
        int t = (tid >= o) ? sh[tid - o] : 0;
        __syncthreads();
        sh[tid] += t;
        __syncthreads();
    }
    if (gid < NN) g_off[gid] = sh[tid] - v;   // exclusive
    if (tid == 1023) g_bsum[blockIdx.x] = sh[1023];
}

__global__ void k_scan_top() {
    __shared__ int sh[64];
    int tid = threadIdx.x;
    const int nB = (NN + 1023) / 1024;   // 49
    int v = (tid < nB) ? g_bsum[tid] : 0;
    sh[tid] = v;
    __syncthreads();
    for (int o = 1; o < 64; o <<= 1) {
        int t = (tid >= o) ? sh[tid - o] : 0;
        __syncthreads();
        sh[tid] += t;
        __syncthreads();
    }
    if (tid < nB) g_bsum[tid] = sh[tid] - v;  // exclusive
}

__global__ void k_scan_add() {
    int i = blockIdx.x * blockDim.x + threadIdx.x;
    if (i < NN) {
        int o = g_off[i] + g_bsum[i >> 10];
        g_off[i] = o;
        g_cur[i] = o;
    }
    if (i == 0) g_off[NN] = NE;
}

__global__ void k_scatter() {
    int e = blockIdx.x * blockDim.x + threadIdx.x;
    if (e < NE) {
        int d = g_dst[e];
        int p = atomicAdd(&g_cur[d], 1);
        g_csr[p] = g_src[e];
    }
}

// ---------------- softmax aggregation: warp per node ----------------
// src_sel: 0 = x (kernel arg), 1 = g_bufA, 2 = g_bufB
__global__ __launch_bounds__(256) void k_agg(const float* __restrict__ xin, int src_sel) {
    const float* x = (src_sel == 0) ? xin : (src_sel == 1) ? g_bufA : g_bufB;
    int w = (blockIdx.x * blockDim.x + threadIdx.x) >> 5;
    if (w >= NN) return;
    int lane = threadIdx.x & 31;
    int beg = g_off[w], end = g_off[w + 1];
    int c = lane * 2;

    float m0 = -1e30f, m1 = -1e30f;
    for (int j = beg; j < end; j++) {
        int s = g_csr[j];
        float2 v = *(const float2*)(x + (size_t)s * DIN + c);
        float v0 = fmaxf(v.x, 0.f) + 1e-7f;
        float v1 = fmaxf(v.y, 0.f) + 1e-7f;
        m0 = fmaxf(m0, v0);
        m1 = fmaxf(m1, v1);
    }
    float d0 = 0.f, d1 = 0.f, n0 = 0.f, n1 = 0.f;
    for (int j = beg; j < end; j++) {
        int s = g_csr[j];
        float2 v = *(const float2*)(x + (size_t)s * DIN + c);
        float v0 = fmaxf(v.x, 0.f) + 1e-7f;
        float v1 = fmaxf(v.y, 0.f) + 1e-7f;
        float e0 = __expf(v0 - m0);
        float e1 = __expf(v1 - m1);
        d0 += e0; d1 += e1;
        n0 += v0 * e0; n1 += v1 * e1;
    }
    float2 xc = *(const float2*)(x + (size_t)w * DIN + c);
    float2 o;
    o.x = n0 / (d0 + 1e-16f) + xc.x;
    o.y = n1 / (d1 + 1e-16f) + xc.y;
    *(float2*)(g_agg + (size_t)w * DIN + c) = o;
}

// ---------------- BN helpers ----------------
__global__ void k_zero_bn() {
    int i = threadIdx.x;
    if (i < 2 * DH) g_bn[i] = 0.f;
}

__global__ void k_bn_fin(const float* __restrict__ gamma, const float* __restrict__ beta) {
    int c = threadIdx.x;
    float mu  = g_bn[c] * (1.0f / NN);
    float var = g_bn[DH + c] * (1.0f / NN) - mu * mu;
    float rs  = rsqrtf(var + 1e-5f);
    float sc  = rs * gamma[c];
    g_scale[c] = sc;
    g_shift[c] = beta[c] - mu * sc;
}

// ---------------- GEMM1: h1 = agg @ W1 + b1, fused BN-stat accumulation ----------------
// tile 128 rows x 128 cols, K=64. 256 threads, micro 8x8.
#define G1_AS_LD 68
__global__ __launch_bounds__(256) void k_gemm1(const float* __restrict__ W1,
                                               const float* __restrict__ b1) {
    extern __shared__ float sm[];
    float* As   = sm;                       // [128][68]
    float* Ws   = sm + 128 * G1_AS_LD;      // [64][128]
    float* csum = Ws + 64 * DH;             // [128]
    float* csq  = csum + DH;                // [128]

    int tid  = threadIdx.x;
    int row0 = blockIdx.x * 128;

    if (tid < DH) { csum[tid] = 0.f; csq[tid] = 0.f; }

    // load A tile (row-major, pad 68) : 2048 float4
    #pragma unroll
    for (int i = 0; i < 8; i++) {
        int f = tid + i * 256;
        int r = f >> 4, k4 = f & 15;
        int row = row0 + r;
        float4 v = make_float4(0.f, 0.f, 0.f, 0.f);
        if (row < NN) v = *(const float4*)(g_agg + (size_t)row * DIN + k4 * 4);
        *(float4*)&As[r * G1_AS_LD + k4 * 4] = v;
    }
    // load W1 (64x128) : 2048 float4
    #pragma unroll
    for (int i = 0; i < 8; i++) {
        int f = tid + i * 256;
        int k = f >> 5, c4 = f & 31;
        *(float4*)&Ws[k * DH + c4 * 4] = *(const float4*)(W1 + k * DH + c4 * 4);
    }
    __syncthreads();

    int tx = tid & 15;   // 8 cols each
    int ty = tid >> 4;   // 8 rows each
    float acc[8][8];
    #pragma unroll
    for (int i = 0; i < 8; i++)
        #pragma unroll
        for (int j = 0; j < 8; j++) acc[i][j] = 0.f;

    #pragma unroll 8
    for (int k = 0; k < DIN; k++) {
        float4 w0 = *(float4*)&Ws[k * DH + tx * 8];
        float4 w1 = *(float4*)&Ws[k * DH + tx * 8 + 4];
        float wv[8] = {w0.x, w0.y, w0.z, w0.w, w1.x, w1.y, w1.z, w1.w};
        #pragma unroll
        for (int i = 0; i < 8; i++) {
            float a = As[(ty * 8 + i) * G1_AS_LD + k];
            #pragma unroll
            for (int j = 0; j < 8; j++) acc[i][j] = fmaf(a, wv[j], acc[i][j]);
        }
    }

    int col0 = tx * 8;
    float4 bb0 = *(const float4*)(b1 + col0);
    float4 bb1 = *(const float4*)(b1 + col0 + 4);
    float bv[8] = {bb0.x, bb0.y, bb0.z, bb0.w, bb1.x, bb1.y, bb1.z, bb1.w};

    float lsum[8], lsq[8];
    #pragma unroll
    for (int j = 0; j < 8; j++) { lsum[j] = 0.f; lsq[j] = 0.f; }

    #pragma unroll
    for (int i = 0; i < 8; i++) {
        int row = row0 + ty * 8 + i;
        if (row < NN) {
            float o[8];
            #pragma unroll
            for (int j = 0; j < 8; j++) {
                float v = acc[i][j] + bv[j];
                o[j] = v;
                lsum[j] += v;
                lsq[j]  += v * v;
            }
            *(float4*)(g_h1 + (size_t)row * DH + col0)     = make_float4(o[0], o[1], o[2], o[3]);
            *(float4*)(g_h1 + (size_t)row * DH + col0 + 4) = make_float4(o[4], o[5], o[6], o[7]);
        }
    }
    #pragma unroll
    for (int j = 0; j < 8; j++) {
        atomicAdd(&csum[col0 + j], lsum[j]);
        atomicAdd(&csq[col0 + j],  lsq[j]);
    }
    __syncthreads();
    if (tid < DH) {
        atomicAdd(&g_bn[tid], csum[tid]);
        atomicAdd(&g_bn[DH + tid], csq[tid]);
    }
}

// ---------------- mish ----------------
__device__ __forceinline__ float mishf(float v) {
    float e  = __expf(v);
    float sp = (v > 15.f) ? v : log1pf(e);
    return v * tanhf(sp);
}

// ---------------- GEMM2: out = relu(BN(h1)) @ W2 + b2 (+mish) ----------------
// tile 128 rows x 64 cols, K=128. 256 threads, micro 8x4.
// dst_sel: 0 = g_bufA, 1 = g_bufB, 2 = out (kernel arg)
#define G2_AS_LD 132
__global__ __launch_bounds__(256) void k_gemm2(const float* __restrict__ W2,
                                               const float* __restrict__ b2,
                                               float* __restrict__ outp,
                                               int dst_sel, int do_mish) {
    extern __shared__ float sm[];
    float* As  = sm;                       // [128][132]
    float* Ws  = sm + 128 * G2_AS_LD;      // [128][64]
    float* ssc = Ws + DH * DIN;            // [128]
    float* ssh = ssc + DH;                 // [128]

    float* out = (dst_sel == 0) ? g_bufA : (dst_sel == 1) ? g_bufB : outp;

    int tid = threadIdx.x;
    if (tid < DH) { ssc[tid] = g_scale[tid]; ssh[tid] = g_shift[tid]; }
    __syncthreads();

    int row0 = blockIdx.x * 128;

    // load + transform A tile (BN + relu fused) : 4096 float4
    #pragma unroll
    for (int i = 0; i < 16; i++) {
        int f = tid + i * 256;
        int r = f >> 5, k4 = f & 31;
        int row = row0 + r;
        float4 v = make_float4(0.f, 0.f, 0.f, 0.f);
        if (row < NN) v = *(const float4*)(g_h1 + (size_t)row * DH + k4 * 4);
        int c = k4 * 4;
        float4 t;
        t.x = fmaxf(fmaf(v.x, ssc[c + 0], ssh[c + 0]), 0.f);
        t.y = fmaxf(fmaf(v.y, ssc[c + 1], ssh[c + 1]), 0.f);
        t.z = fmaxf(fmaf(v.z, ssc[c + 2], ssh[c + 2]), 0.f);
        t.w = fmaxf(fmaf(v.w, ssc[c + 3], ssh[c + 3]), 0.f);
        *(float4*)&As[r * G2_AS_LD + c] = t;
    }
    // load W2 (128x64) : 2048 float4
    #pragma unroll
    for (int i = 0; i < 8; i++) {
        int f = tid + i * 256;
        int k = f >> 4, c4 = f & 15;
        *(float4*)&Ws[k * DIN + c4 * 4] = *(const float4*)(W2 + k * DIN + c4 * 4);
    }
    __syncthreads();

    int tx = tid & 15;   // 4 cols each
    int ty = tid >> 4;   // 8 rows each
    float acc[8][4];
    #pragma unroll
    for (int i = 0; i < 8; i++)
        #pragma unroll
        for (int j = 0; j < 4; j++) acc[i][j] = 0.f;

    #pragma unroll 8
    for (int k = 0; k < DH; k++) {
        float4 wv = *(float4*)&Ws[k * DIN + tx * 4];
        #pragma unroll
        for (int i = 0; i < 8; i++) {
            float a = As[(ty * 8 + i) * G2_AS_LD + k];
            acc[i][0] = fmaf(a, wv.x, acc[i][0]);
            acc[i][1] = fmaf(a, wv.y, acc[i][1]);
            acc[i][2] = fmaf(a, wv.z, acc[i][2]);
            acc[i][3] = fmaf(a, wv.w, acc[i][3]);
        }
    }

    int col0 = tx * 4;
    float4 bb = *(const float4*)(b2 + col0);
    #pragma unroll
    for (int i = 0; i < 8; i++) {
        int row = row0 + ty * 8 + i;
        if (row < NN) {
            float4 o;
            o.x = acc[i][0] + bb.x;
            o.y = acc[i][1] + bb.y;
            o.z = acc[i][2] + bb.z;
            o.w = acc[i][3] + bb.w;
            if (do_mish) {
                o.x = mishf(o.x); o.y = mishf(o.y);
                o.z = mishf(o.z); o.w = mishf(o.w);
            }
            *(float4*)(out + (size_t)row * DIN + col0) = o;
        }
    }
}

// ---------------- host launch ----------------
extern "C" void kernel_launch(void* const* d_in, const int* in_sizes, int n_in,
                              void* d_out, int out_size) {
    const float* x     = (const float*)d_in[0];
    const void*  ei    = (const void*)d_in[1];
    const float* W1    = (const float*)d_in[2];
    const float* b1    = (const float*)d_in[3];
    const float* gamma = (const float*)d_in[4];
    const float* beta  = (const float*)d_in[5];
    const float* W2    = (const float*)d_in[6];
    const float* b2    = (const float*)d_in[7];
    float*       out   = (float*)d_out;

    const int SM1 = (128 * G1_AS_LD + 64 * DH + 2 * DH) * sizeof(float);   // ~68.6 KB
    const int SM2 = (128 * G2_AS_LD + DH * DIN + 2 * DH) * sizeof(float);  // ~101.4 KB
    cudaFuncSetAttribute(k_gemm1, cudaFuncAttributeMaxDynamicSharedMemorySize, SM1);
    cudaFuncSetAttribute(k_gemm2, cudaFuncAttributeMaxDynamicSharedMemorySize, SM2);

    // ---- edge normalize + CSR build ----
    k_detect<<<1, 32>>>(ei);
    k_convert<<<(NE + 255) / 256, 256>>>(ei);
    k_zero_deg<<<(NN + 255) / 256, 256>>>();
    k_hist<<<(NE + 255) / 256, 256>>>();
    k_scan_local<<<(NN + 1023) / 1024, 1024>>>();
    k_scan_top<<<1, 64>>>();
    k_scan_add<<<(NN + 255) / 256, 256>>>();
    k_scatter<<<(NE + 255) / 256, 256>>>();

    const int AGG_BLOCKS  = (NN * 32 + 255) / 256;       // warp per node
    const int GEMM_BLOCKS = (NN + 127) / 128;            // 391

    for (int l = 0; l < 4; l++) {
        int src_sel = (l == 0) ? 0 : ((l & 1) ? 1 : 2);  // layer1 reads bufA, layer2 reads bufB...
        int dst_sel = (l == 3) ? 2 : (l & 1);            // layer0->bufA(0), layer1->bufB(1), layer2->bufA(0), layer3->out(2)

        k_agg<<<AGG_BLOCKS, 256>>>(x, src_sel);
        k_zero_bn<<<1, 256>>>();
        k_gemm1<<<GEMM_BLOCKS, 256, SM1>>>(W1 + (size_t)l * DIN * DH, b1 + (size_t)l * DH);
        k_bn_fin<<<1, DH>>>(gamma + (size_t)l * DH, beta + (size_t)l * DH);
        k_gemm2<<<GEMM_BLOCKS, 256, SM2>>>(W2 + (size_t)l * DH * DIN, b2 + (size_t)l * DIN,
                                           out, dst_sel, (l < 3) ? 1 : 0);
    }
}

// round 6
// speedup vs baseline: 1.0941x; 1.0941x over previous
#include <cuda_runtime.h>
#include <cuda_bf16.h>
#include <math.h>
#include <stdint.h>

#define NN 50000
#define NE 800000
#define DIN 64
#define DH  128

// ---------------- device scratch (static, no allocation) ----------------
__device__ float g_bufA[NN * DIN];
__device__ float g_bufB[NN * DIN];
__device__ float g_agg[NN * DIN];
__device__ float g_h1[NN * DH];
__device__ int   g_src[NE];
__device__ int   g_dst[NE];
__device__ int   g_deg[NN];
__device__ int   g_off[NN + 1];
__device__ int   g_cur[NN];
__device__ int   g_csr[NE];
__device__ int   g_bsum[64];
__device__ int   g_is32;
__device__ float g_bn[2 * DH];
__device__ float g_scale[DH];
__device__ float g_shift[DH];
// baked weights in mma-fragment order: uint4 = {b0hi, b1hi, b0lo, b1lo}
// g_w1f[l][kstep(4)][n8(16)][lane(32)]   g_w2f[l][kstep(8)][n8(8)][lane(32)]
__device__ uint4 g_w1f[4][4][16][32];
__device__ uint4 g_w2f[4][8][8][32];

// ================= mma helpers (sm_80+ PTX, compiles for compute_103) =================
__device__ __forceinline__ uint32_t smem_u32(const void* p) {
    uint32_t a;
    asm("{ .reg .u64 t; cvta.to.shared.u64 t, %1; cvt.u32.u64 %0, t; }" : "=r"(a) : "l"(p));
    return a;
}
__device__ __forceinline__ void ldmat4(uint32_t* r, uint32_t addr) {
    asm volatile("ldmatrix.sync.aligned.m8n8.x4.shared.b16 {%0,%1,%2,%3}, [%4];"
                 : "=r"(r[0]), "=r"(r[1]), "=r"(r[2]), "=r"(r[3]) : "r"(addr));
}
__device__ __forceinline__ void mma_bf16(float* d, const uint32_t* a, uint32_t b0, uint32_t b1) {
    asm volatile("mma.sync.aligned.m16n8k16.row.col.f32.bf16.bf16.f32 "
                 "{%0,%1,%2,%3}, {%4,%5,%6,%7}, {%8,%9}, {%0,%1,%2,%3};"
                 : "+f"(d[0]), "+f"(d[1]), "+f"(d[2]), "+f"(d[3])
                 : "r"(a[0]), "r"(a[1]), "r"(a[2]), "r"(a[3]), "r"(b0), "r"(b1));
}
__device__ __forceinline__ uint32_t pack_hi2(float x, float y, uint32_t& lo) {
    __nv_bfloat16 hx = __float2bfloat16(x), hy = __float2bfloat16(y);
    __nv_bfloat16 lx = __float2bfloat16(x - __bfloat162float(hx));
    __nv_bfloat16 ly = __float2bfloat16(y - __bfloat162float(hy));
    lo = ((uint32_t)__bfloat16_as_ushort(ly) << 16) | __bfloat16_as_ushort(lx);
    return ((uint32_t)__bfloat16_as_ushort(hy) << 16) | __bfloat16_as_ushort(hx);
}

// ---------------- edge dtype detect + normalize ----------------
__global__ void k_detect(const void* __restrict__ ei) {
    if (threadIdx.x == 0 && blockIdx.x == 0) {
        const long long* p = (const long long*)ei;
        int is32 = 0;
        for (int i = 0; i < 256; i++) {
            long long v = p[i];
            if (v < 0 || v >= NN) { is32 = 1; break; }
        }
        g_is32 = is32;
    }
}

__global__ void k_convert(const void* __restrict__ ei) {
    int e = blockIdx.x * blockDim.x + threadIdx.x;
    if (e >= NE) return;
    int s, d;
    if (g_is32) {
        const int* p = (const int*)ei;
        s = p[e]; d = p[NE + e];
    } else {
        const long long* p = (const long long*)ei;
        s = (int)p[e]; d = (int)p[NE + e];
    }
    s = min(max(s, 0), NN - 1);
    d = min(max(d, 0), NN - 1);
    g_src[e] = s;
    g_dst[e] = d;
}

// ---------------- CSR build ----------------
__global__ void k_zero_deg() {
    int i = blockIdx.x * blockDim.x + threadIdx.x;
    if (i < NN) g_deg[i] = 0;
}
__global__ void k_hist() {
    int e = blockIdx.x * blockDim.x + threadIdx.x;
    if (e < NE) atomicAdd(&g_deg[g_dst[e]], 1);
}
__global__ void k_scan_local() {
    __shared__ int sh[1024];
    int tid = threadIdx.x;
    int gid = blockIdx.x * 1024 + tid;
    int v = (gid < NN) ? g_deg[gid] : 0;
    sh[tid] = v;
    __syncthreads();
    for (int o = 1; o < 1024; o <<= 1) {
        int t = (tid >= o) ? sh[tid - o] : 0;
        __syncthreads();
        sh[tid] += t;
        __syncthreads();
    }
    if (gid < NN) g_off[gid] = sh[tid] - v;
    if (tid == 1023) g_bsum[blockIdx.x] = sh[1023];
}
__global__ void k_scan_top() {
    __shared__ int sh[64];
    int tid = threadIdx.x;
    const int nB = (NN + 1023) / 1024;
    int v = (tid < nB) ? g_bsum[tid] : 0;
    sh[tid] = v;
    __syncthreads();
    for (int o = 1; o < 64; o <<= 1) {
        int t = (tid >= o) ? sh[tid - o] : 0;
        __syncthreads();
        sh[tid] += t;
        __syncthreads();
    }
    if (tid < nB) g_bsum[tid] = sh[tid] - v;
}
__global__ void k_scan_add() {
    int i = blockIdx.x * blockDim.x + threadIdx.x;
    if (i < NN) {
        int o = g_off[i] + g_bsum[i >> 10];
        g_off[i] = o;
        g_cur[i] = o;
    }
    if (i == 0) g_off[NN] = NE;
}
__global__ void k_scatter() {
    int e = blockIdx.x * blockDim.x + threadIdx.x;
    if (e < NE) {
        int d = g_dst[e];
        int p = atomicAdd(&g_cur[d], 1);
        g_csr[p] = g_src[e];
    }
}

// ---------------- weight bake: fp32 -> bf16 hi/lo fragment-order uint4 ----------------
// fragment element for lane t, reg r: n = n8*8 + t/4, k = kstep*16 + r*8 + 2*(t%4)+{0,1}
__global__ void k_prepw(const float* __restrict__ W1, const float* __restrict__ W2) {
    int i = blockIdx.x * blockDim.x + threadIdx.x;
    if (i < 8192) {
        int lane = i & 31, n8 = (i >> 5) & 15, kstep = (i >> 9) & 3, l = i >> 11;
        int n = n8 * 8 + (lane >> 2);
        int k0 = kstep * 16 + 2 * (lane & 3);
        const float* W = W1 + (size_t)l * 8192;       // [k=64][n=128]
        float f00 = W[(k0 + 0) * 128 + n], f01 = W[(k0 + 1) * 128 + n];
        float f10 = W[(k0 + 8) * 128 + n], f11 = W[(k0 + 9) * 128 + n];
        uint4 w;
        w.x = pack_hi2(f00, f01, w.z);
        w.y = pack_hi2(f10, f11, w.w);
        g_w1f[l][kstep][n8][lane] = w;
    } else if (i < 16384) {
        int j = i - 8192;
        int lane = j & 31, n8 = (j >> 5) & 7, kstep = (j >> 8) & 7, l = j >> 11;
        int n = n8 * 8 + (lane >> 2);
        int k0 = kstep * 16 + 2 * (lane & 3);
        const float* W = W2 + (size_t)l * 8192;       // [k=128][n=64]
        float f00 = W[(k0 + 0) * 64 + n], f01 = W[(k0 + 1) * 64 + n];
        float f10 = W[(k0 + 8) * 64 + n], f11 = W[(k0 + 9) * 64 + n];
        uint4 w;
        w.x = pack_hi2(f00, f01, w.z);
        w.y = pack_hi2(f10, f11, w.w);
        g_w2f[l][kstep][n8][lane] = w;
    }
}

// ---------------- softmax aggregation: warp per node, single-pass online ----------------
__global__ __launch_bounds__(256) void k_agg(const float* __restrict__ xin, int src_sel) {
    const float* x = (src_sel == 0) ? xin : (src_sel == 1) ? g_bufA : g_bufB;
    int w = (blockIdx.x * blockDim.x + threadIdx.x) >> 5;
    if (w >= NN) return;
    int lane = threadIdx.x & 31;
    int beg = g_off[w], end = g_off[w + 1];
    int c = lane * 2;

    float m0 = -1e30f, m1 = -1e30f;
    float d0 = 0.f, d1 = 0.f, n0 = 0.f, n1 = 0.f;
    #pragma unroll 2
    for (int j = beg; j < end; j++) {
        int s = g_csr[j];
        float2 v = *(const float2*)(x + (size_t)s * DIN + c);
        float v0 = fmaxf(v.x, 0.f) + 1e-7f;
        float v1 = fmaxf(v.y, 0.f) + 1e-7f;
        float nm0 = fmaxf(m0, v0), nm1 = fmaxf(m1, v1);
        float s0 = __expf(m0 - nm0), s1 = __expf(m1 - nm1);
        float e0 = __expf(v0 - nm0), e1 = __expf(v1 - nm1);
        d0 = d0 * s0 + e0;  n0 = n0 * s0 + v0 * e0;  m0 = nm0;
        d1 = d1 * s1 + e1;  n1 = n1 * s1 + v1 * e1;  m1 = nm1;
    }
    float2 xc = *(const float2*)(x + (size_t)w * DIN + c);
    float2 o;
    o.x = n0 / (d0 + 1e-16f) + xc.x;
    o.y = n1 / (d1 + 1e-16f) + xc.y;
    *(float2*)(g_agg + (size_t)w * DIN + c) = o;
}

// ---------------- BN ----------------
__global__ void k_zero_bn() {
    int i = threadIdx.x;
    if (i < 2 * DH) g_bn[i] = 0.f;
}
__global__ __launch_bounds__(256) void k_bnstat() {
    __shared__ float ss[256], sq[256];
    int col = threadIdx.x & 127;
    int half = threadIdx.x >> 7;
    float s = 0.f, q = 0.f;
    for (int r = blockIdx.x * 2 + half; r < NN; r += gridDim.x * 2) {
        float v = g_h1[(size_t)r * DH + col];
        s += v; q += v * v;
    }
    ss[threadIdx.x] = s; sq[threadIdx.x] = q;
    __syncthreads();
    if (half == 0) {
        atomicAdd(&g_bn[col], ss[col] + ss[col + 128]);
        atomicAdd(&g_bn[DH + col], sq[col] + sq[col + 128]);
    }
}
__global__ void k_bn_fin(const float* __restrict__ gamma, const float* __restrict__ beta) {
    int c = threadIdx.x;
    float mu  = g_bn[c] * (1.0f / NN);
    float var = g_bn[DH + c] * (1.0f / NN) - mu * mu;
    float rs  = rsqrtf(var + 1e-5f);
    float sc  = rs * gamma[c];
    g_scale[c] = sc;
    g_shift[c] = beta[c] - mu * sc;
    g_bn[c] = 0.f;               // self-zero for next layer
    g_bn[DH + c] = 0.f;
}

// ---------------- GEMM1 (mma.sync bf16 split): h1 = agg @ W1 + b1  [128/blk x 128 x K64] ----------------
// smem: Ahi[128][72] bf16 + Alo[128][72] bf16  (72 = 64 + 8 pad -> 144B stride, ldmatrix conflict-free)
#define LDA1 72
__global__ __launch_bounds__(256) void k_gemm1_mma(const float* __restrict__ b1, int layer) {
    __shared__ __nv_bfloat16 Ahi[128 * LDA1];
    __shared__ __nv_bfloat16 Alo[128 * LDA1];
    int tid = threadIdx.x, lane = tid & 31, wid = tid >> 5;
    int row0 = blockIdx.x * 128;

    // convert A tile: 128 x 64 fp32 -> hi/lo bf16
    #pragma unroll
    for (int it = 0; it < 16; it++) {
        int f = tid + it * 256;
        int r = f >> 5, c2 = f & 31;
        int row = row0 + r;
        float2 v = make_float2(0.f, 0.f);
        if (row < NN) v = *(const float2*)(g_agg + (size_t)row * DIN + c2 * 2);
        uint32_t lp, hp = pack_hi2(v.x, v.y, lp);
        *(uint32_t*)&Ahi[r * LDA1 + c2 * 2] = hp;
        *(uint32_t*)&Alo[r * LDA1 + c2 * 2] = lp;
    }
    __syncthreads();

    int wm = wid & 3, wn = wid >> 2;      // warp tile: 32 rows x 64 cols
    int mBase = wm * 32, nBase = wn * 64;
    uint32_t a_hi = smem_u32(Ahi), a_lo = smem_u32(Alo);

    float acc[2][8][4];
    #pragma unroll
    for (int tm = 0; tm < 2; tm++)
        #pragma unroll
        for (int tn = 0; tn < 8; tn++)
            #pragma unroll
            for (int q = 0; q < 4; q++) acc[tm][tn][q] = 0.f;

    int lrow = lane & 15;
    int lkof = (lane >> 4) << 3;
    #pragma unroll
    for (int ks = 0; ks < 4; ks++) {
        uint32_t ah[2][4], al[2][4];
        #pragma unroll
        for (int tm = 0; tm < 2; tm++) {
            uint32_t off = ((mBase + tm * 16 + lrow) * LDA1 + ks * 16 + lkof) * 2;
            ldmat4(ah[tm], a_hi + off);
            ldmat4(al[tm], a_lo + off);
        }
        uint4 w[8];
        #pragma unroll
        for (int tn = 0; tn < 8; tn++)
            w[tn] = g_w1f[layer][ks][wn * 8 + tn][lane];
        #pragma unroll
        for (int tm = 0; tm < 2; tm++)
            #pragma unroll
            for (int tn = 0; tn < 8; tn++) {
                mma_bf16(acc[tm][tn], ah[tm], w[tn].x, w[tn].y);
                mma_bf16(acc[tm][tn], ah[tm], w[tn].z, w[tn].w);
                mma_bf16(acc[tm][tn], al[tm], w[tn].x, w[tn].y);
            }
    }

    // epilogue: + bias, store h1
    int qrow = lane >> 2, qcol = (lane & 3) * 2;
    #pragma unroll
    for (int tm = 0; tm < 2; tm++) {
        int r0 = row0 + mBase + tm * 16 + qrow;
        #pragma unroll
        for (int tn = 0; tn < 8; tn++) {
            int c = nBase + tn * 8 + qcol;
            float bx = b1[c], by = b1[c + 1];
            if (r0 < NN)
                *(float2*)(g_h1 + (size_t)r0 * DH + c) = make_float2(acc[tm][tn][0] + bx, acc[tm][tn][1] + by);
            if (r0 + 8 < NN)
                *(float2*)(g_h1 + (size_t)(r0 + 8) * DH + c) = make_float2(acc[tm][tn][2] + bx, acc[tm][tn][3] + by);
        }
    }
}

// ---------------- mish ----------------
__device__ __forceinline__ float mishf(float v) {
    float e  = __expf(v);
    float sp = (v > 15.f) ? v : log1pf(e);
    return v * tanhf(sp);
}

// ---------------- GEMM2 (mma.sync bf16 split): out = relu(BN(h1)) @ W2 + b2 (+mish) ----------------
// [128/blk x 64 x K128]; smem Ahi/Alo [128][136] (272B stride)
#define LDA2 136
__global__ __launch_bounds__(256) void k_gemm2_mma(const float* __restrict__ b2,
                                                   float* __restrict__ outp,
                                                   int layer, int dst_sel, int do_mish) {
    __shared__ __nv_bfloat16 Ahi[128 * LDA2];
    __shared__ __nv_bfloat16 Alo[128 * LDA2];
    __shared__ float ssc[DH], ssh[DH];
    int tid = threadIdx.x, lane = tid & 31, wid = tid >> 5;
    float* out = (dst_sel == 0) ? g_bufA : (dst_sel == 1) ? g_bufB : outp;

    if (tid < DH) { ssc[tid] = g_scale[tid]; ssh[tid] = g_shift[tid]; }
    __syncthreads();

    int row0 = blockIdx.x * 128;
    // convert A tile: 128 x 128, BN + relu fused
    #pragma unroll
    for (int it = 0; it < 32; it++) {
        int f = tid + it * 256;
        int r = f >> 6, c2 = f & 63;
        int row = row0 + r;
        float2 v = make_float2(0.f, 0.f);
        if (row < NN) v = *(const float2*)(g_h1 + (size_t)row * DH + c2 * 2);
        int c = c2 * 2;
        float a0 = fmaxf(fmaf(v.x, ssc[c], ssh[c]), 0.f);
        float a1 = fmaxf(fmaf(v.y, ssc[c + 1], ssh[c + 1]), 0.f);
        uint32_t lp, hp = pack_hi2(a0, a1, lp);
        *(uint32_t*)&Ahi[r * LDA2 + c] = hp;
        *(uint32_t*)&Alo[r * LDA2 + c] = lp;
    }
    __syncthreads();

    int wm = wid & 3, wn = wid >> 2;      // warp tile: 32 rows x 32 cols
    int mBase = wm * 32, nBase = wn * 32;
    uint32_t a_hi = smem_u32(Ahi), a_lo = smem_u32(Alo);

    float acc[2][4][4];
    #pragma unroll
    for (int tm = 0; tm < 2; tm++)
        #pragma unroll
        for (int tn = 0; tn < 4; tn++)
            #pragma unroll
            for (int q = 0; q < 4; q++) acc[tm][tn][q] = 0.f;

    int lrow = lane & 15;
    int lkof = (lane >> 4) << 3;
    #pragma unroll
    for (int ks = 0; ks < 8; ks++) {
        uint32_t ah[2][4], al[2][4];
        #pragma unroll
        for (int tm = 0; tm < 2; tm++) {
            uint32_t off = ((mBase + tm * 16 + lrow) * LDA2 + ks * 16 + lkof) * 2;
            ldmat4(ah[tm], a_hi + off);
            ldmat4(al[tm], a_lo + off);
        }
        uint4 w[4];
        #pragma unroll
        for (int tn = 0; tn < 4; tn++)
            w[tn] = g_w2f[layer][ks][wn * 4 + tn][lane];
        #pragma unroll
        for (int tm = 0; tm < 2; tm++)
            #pragma unroll
            for (int tn = 0; tn < 4; tn++) {
                mma_bf16(acc[tm][tn], ah[tm], w[tn].x, w[tn].y);
                mma_bf16(acc[tm][tn], ah[tm], w[tn].z, w[tn].w);
                mma_bf16(acc[tm][tn], al[tm], w[tn].x, w[tn].y);
            }
    }

    int qrow = lane >> 2, qcol = (lane & 3) * 2;
    #pragma unroll
    for (int tm = 0; tm < 2; tm++) {
        int r0 = row0 + mBase + tm * 16 + qrow;
        #pragma unroll
        for (int tn = 0; tn < 4; tn++) {
            int c = nBase + tn * 8 + qcol;
            float bx = b2[c], by = b2[c + 1];
            float2 o0 = make_float2(acc[tm][tn][0] + bx, acc[tm][tn][1] + by);
            float2 o1 = make_float2(acc[tm][tn][2] + bx, acc[tm][tn][3] + by);
            if (do_mish) {
                o0.x = mishf(o0.x); o0.y = mishf(o0.y);
                o1.x = mishf(o1.x); o1.y = mishf(o1.y);
            }
            if (r0 < NN)     *(float2*)(out + (size_t)r0 * DIN + c) = o0;
            if (r0 + 8 < NN) *(float2*)(out + (size_t)(r0 + 8) * DIN + c) = o1;
        }
    }
}

// ---------------- host launch ----------------
extern "C" void kernel_launch(void* const* d_in, const int* in_sizes, int n_in,
                              void* d_out, int out_size) {
    const float* x     = (const float*)d_in[0];
    const void*  ei    = (const void*)d_in[1];
    const float* W1    = (const float*)d_in[2];
    const float* b1    = (const float*)d_in[3];
    const float* gamma = (const float*)d_in[4];
    const float* beta  = (const float*)d_in[5];
    const float* W2    = (const float*)d_in[6];
    const float* b2    = (const float*)d_in[7];
    float*       out   = (float*)d_out;

    // ---- edge normalize + CSR build + weight bake ----
    k_detect<<<1, 32>>>(ei);
    k_convert<<<(NE + 255) / 256, 256>>>(ei);
    k_zero_deg<<<(NN + 255) / 256, 256>>>();
    k_hist<<<(NE + 255) / 256, 256>>>();
    k_scan_local<<<(NN + 1023) / 1024, 1024>>>();
    k_scan_top<<<1, 64>>>();
    k_scan_add<<<(NN + 255) / 256, 256>>>();
    k_scatter<<<(NE + 255) / 256, 256>>>();
    k_prepw<<<64, 256>>>(W1, W2);
    k_zero_bn<<<1, 256>>>();

    const int AGG_BLOCKS  = (NN * 32 + 255) / 256;
    const int GEMM_BLOCKS = (NN + 127) / 128;   // 391

    for (int l = 0; l < 4; l++) {
        int src_sel = (l == 0) ? 0 : ((l & 1) ? 1 : 2);
        int dst_sel = (l == 3) ? 2 : (l & 1);

        k_agg<<<AGG_BLOCKS, 256>>>(x, src_sel);
        k_gemm1_mma<<<GEMM_BLOCKS, 256>>>(b1 + (size_t)l * DH, l);
        k_bnstat<<<GEMM_BLOCKS, 256>>>();
        k_bn_fin<<<1, DH>>>(gamma + (size_t)l * DH, beta + (size_t)l * DH);
        k_gemm2_mma<<<GEMM_BLOCKS, 256>>>(b2 + (size_t)l * DIN, out, l, dst_sel, (l < 3) ? 1 : 0);
    }
}